// round 10
// baseline (speedup 1.0000x reference)
#include <cuda_runtime.h>

#define PATCH 32
#define MAXP  65536
#define NREAL 3
#define NBLK  1024
#define FLAGBIT 0x40000000

__device__ volatile int g_state[NBLK];   // per-block child-count, FLAGBIT when valid

// ---------------------------------------------------------------------------
// Init: re-zero scan flags each replay (graph-safe, deterministic).
// ---------------------------------------------------------------------------
__global__ void init_kernel() {
    int i = blockIdx.x * 256 + threadIdx.x;
    if (i < NBLK) g_state[i] = 0;
}

// ---------------------------------------------------------------------------
// Fused gate + single-pass scan + writer. 256 threads, 64 patches per block.
// Phase 1: round-9 gate (4 threads/patch, FMA chains, quad shfl_xor).
// Phase 2: publish block aggregate; poll preceding blocks' aggregates (only
//          lower block ids -> no deadlock); warp-0 in-block scan.
// Phase 3: round-9 writer body, 8 warps x 8 patches (x lines are L1-hot).
// Output layout (floats):
//   [0,32T) new_x   [32T,64T) new_mask  [64T,65T) new_size
//   [65T,67T) weights  [67T,69T) expert_idx  [69T,165T) x_final [T,3,32]
// ---------------------------------------------------------------------------
template <bool EVEN>
__global__ void fused_kernel(const float* __restrict__ x,
                             const float* __restrict__ mask,
                             const float4* __restrict__ Wg4,
                             float* __restrict__ out, int P, unsigned T) {
    __shared__ float4 wg4[32];       // 4 experts x 8 quads
    __shared__ int    smeta[64];     // i0 | i1<<8 | lvl<<16
    __shared__ float2 sw2[64];       // top-2 scores
    __shared__ int    sstart[64];    // in-block exclusive child start
    __shared__ int    wsum[8];
    __shared__ int    bofs;

    int t = threadIdx.x, lane = t & 31, wp = t >> 5, qt = t & 3;
    const float4* x4 = (const float4*)x;
    if (t < 32) wg4[t] = Wg4[t];
    __syncthreads();

    int pl = t >> 2;                         // local patch 0..63
    unsigned p = blockIdx.x * 64u + (unsigned)pl;

    // ---------------- Phase 1: gate (round-9 math) ----------------
    float4 xa = x4[p * 8u + qt * 2];
    float4 xb = x4[p * 8u + qt * 2 + 1];
    float d[4];
#pragma unroll
    for (int e = 0; e < 4; e++) {
        float4 wa = wg4[e * 8 + qt * 2];
        float4 wb = wg4[e * 8 + qt * 2 + 1];
        float s = xa.x * wa.x;
        s = fmaf(xa.y, wa.y, s);
        s = fmaf(xa.z, wa.z, s);
        s = fmaf(xa.w, wa.w, s);
        s = fmaf(xb.x, wb.x, s);
        s = fmaf(xb.y, wb.y, s);
        s = fmaf(xb.z, wb.z, s);
        s = fmaf(xb.w, wb.w, s);
        d[e] = s;
    }
#pragma unroll
    for (int e = 0; e < 4; e++) {
        d[e] += __shfl_xor_sync(0xffffffffu, d[e], 1);
        d[e] += __shfl_xor_sync(0xffffffffu, d[e], 2);
    }
    float m = fmaxf(fmaxf(d[0], d[1]), fmaxf(d[2], d[3]));
    float ex[4], ssum = 0.f;
#pragma unroll
    for (int i = 0; i < 4; i++) { ex[i] = expf(d[i] - m); ssum += ex[i]; }
    float inv = 1.f / ssum;
    float sc[4];
#pragma unroll
    for (int i = 0; i < 4; i++) sc[i] = ex[i] * inv;
    int i0 = 0;
#pragma unroll
    for (int i = 1; i < 4; i++) if (sc[i] > sc[i0]) i0 = i;
    int i1 = -1;
#pragma unroll
    for (int i = 0; i < 4; i++)
        if (i != i0 && (i1 < 0 || sc[i] > sc[i1])) i1 = i;
    int lv = -1;
    if (i0 < NREAL) lv = max(lv, i0);
    if (i1 < NREAL) lv = max(lv, i1);
    int lvl = max(lv, 0);

    if (qt == 0) {
        smeta[pl] = i0 | (i1 << 8) | (lvl << 16);
        sw2[pl]   = make_float2(sc[i0], sc[i1]);
    }
    int cnt = (qt == 0) ? (1 << lvl) : 0;
    int ws = __reduce_add_sync(0xffffffffu, cnt);
    if (lane == 0) wsum[wp] = ws;
    __syncthreads();

    // ---------------- Phase 2: publish + poll + in-block scan -------------
    if (t == 0) {
        int agg = 0;
#pragma unroll
        for (int i = 0; i < 8; i++) agg += wsum[i];
        g_state[blockIdx.x] = agg | FLAGBIT;   // single-word publish
    }
    // warp 0: in-block exclusive scan of the 64 patch counts (2 per lane)
    if (wp == 0) {
        int ca = 1 << ((smeta[2 * lane]     >> 16) & 3);
        int cb = 1 << ((smeta[2 * lane + 1] >> 16) & 3);
        int s2 = ca + cb;
        int inc = s2;
#pragma unroll
        for (int o = 1; o < 32; o <<= 1) {
            int u = __shfl_up_sync(0xffffffffu, inc, o);
            if (lane >= o) inc += u;
        }
        int exc = inc - s2;
        sstart[2 * lane]     = exc;
        sstart[2 * lane + 1] = exc + ca;
    }
    // all threads: poll preceding block aggregates
    int pre = 0;
    for (int i = t; i < (int)blockIdx.x; i += 256) {
        int v;
        do { v = g_state[i]; } while (!(v & FLAGBIT));
        pre += v & ~FLAGBIT;
    }
    pre = __reduce_add_sync(0xffffffffu, pre);
    __syncthreads();                 // wsum reuse safe
    if (lane == 0) wsum[wp] = pre;
    __syncthreads();
    if (t == 0) {
        int s = 0;
#pragma unroll
        for (int i = 0; i < 8; i++) s += wsum[i];
        bofs = s;
    }
    __syncthreads();

    // ---------------- Phase 3: writer (round-9 body), 8 patches/warp ------
    for (int k = 0; k < 8; k++) {
        int pl2 = wp * 8 + k;
        unsigned w = blockIdx.x * 64u + (unsigned)pl2;
        int meta = smeta[pl2];
        unsigned start = (unsigned)(bofs + sstart[pl2]);
        int mi0 = meta & 255, mi1 = (meta >> 8) & 255, ml = (meta >> 16) & 3;
        int mcnt = 1 << ml, msz = 32 >> ml;

        // new_x / new_mask: 16B-aligned vector stores
        {
            const float4* xp = (const float4*)x + w * 8u;
            const float4* mp = (const float4*)mask + w * 8u;
            int c = lane >> 3, q = lane & 7;
            bool qv = (q * 4) < msz;
            int gi = qv ? ((c * msz) >> 2) + q : 0;
            float4 gx = xp[gi];
            float4 gm = mp[gi];
            if (!qv) { gx = make_float4(0.f,0.f,0.f,0.f);
                       gm = make_float4(0.f,0.f,0.f,0.f); }
            if (c < mcnt) {
                float4* out4 = (float4*)out;
                unsigned idx4 = (start + c) * 8u + q;
                out4[idx4] = gx;
                out4[T * 8u + idx4] = gm;
            }
        }
        // small fields
        float* ps = out + T * 64u + start;
        float* pw = out + T * 65u + start * 2u + lane;
        float* pe = out + T * 67u + start * 2u + lane;
        if (lane < (unsigned)mcnt) ps[lane] = (float)msz;
        if (lane < (unsigned)(mcnt * 2)) {
            float2 wv = sw2[pl2];
            pw[0] = (lane & 1) ? wv.y : wv.x;
            pe[0] = (float)((lane & 1) ? mi1 : mi0);
        }
        // x_final
        if (EVEN) {
            unsigned q16 = lane & 15u, h = lane >> 4;
            float2 xw = ((const float2*)x)[w * 16u + q16];
            float2 mw = ((const float2*)mask)[w * 16u + q16];
            float2 pm2 = make_float2(xw.x * mw.x, xw.y * mw.y);
            const float2 z2 = make_float2(0.f, 0.f);
            int rows = 3 * mcnt;
            int j0 = (int)(q16 * 2u);
            unsigned b2 = (T >> 1) * 69u + start * 48u + q16;
#pragma unroll
            for (int rb = 0; rb < 12; rb += 2) {
                if (rb >= rows) break;
                int row = rb + (int)h;
                int c = (row * 11) >> 5;       // row/3 for row<12
                int l = row - 3 * c;
                bool on = false;
                if (l == ml) {
                    int lo = c * msz; on = (j0 >= lo) & (j0 < lo + msz);
                } else if (ml >= 1 && l == ml - 1) {
                    int lo = (c >> 1) * (msz * 2);
                    on = (j0 >= lo) & (j0 < lo + msz * 2);
                }
                float2 v = on ? pm2 : z2;
                if (row < rows) ((float2*)out)[b2 + (unsigned)row * 16u] = v;
            }
        } else {
            float xv = x[w * 32u + lane];
            float mv = mask[w * 32u + lane];
            float pm = xv * mv;
            float* pf = out + T * 69u + start * 96u + lane;
            switch (ml) {
            case 0:
                pf[0] = pm;  pf[32] = 0.f;  pf[64] = 0.f;
                break;
            case 1: {
                bool lo = lane < 16, hi = !lo;
                pf[0]  = pm;  pf[32]  = lo ? pm : 0.f;  pf[64]  = 0.f;
                pf[96] = pm;  pf[128] = hi ? pm : 0.f;  pf[160] = 0.f;
                break;
            }
            default: {
                bool h0 = lane < 16, h1 = !h0;
                bool o0 = lane < 8, o1 = (lane >= 8) & h0;
                bool o2 = (lane >= 16) & (lane < 24), o3 = lane >= 24;
                pf[0]   = 0.f;  pf[32]  = h0 ? pm : 0.f;  pf[64]  = o0 ? pm : 0.f;
                pf[96]  = 0.f;  pf[128] = h0 ? pm : 0.f;  pf[160] = o1 ? pm : 0.f;
                pf[192] = 0.f;  pf[224] = h1 ? pm : 0.f;  pf[256] = o2 ? pm : 0.f;
                pf[288] = 0.f;  pf[320] = h1 ? pm : 0.f;  pf[352] = o3 ? pm : 0.f;
                break;
            }
            }
        }
    }
}

// ---------------------------------------------------------------------------
extern "C" void kernel_launch(void* const* d_in, const int* in_sizes, int n_in,
                              void* d_out, int out_size) {
    const float* x    = (const float*)d_in[0];
    const float* mask = (const float*)d_in[1];
    const float* Wg   = (const float*)d_in[2];
    float* out = (float*)d_out;

    int n = in_sizes[0];
    int P = n / PATCH;                 // 65536 (P % 64 == 0)
    unsigned T = (unsigned)(out_size / 165);

    init_kernel<<<(NBLK + 255) / 256, 256>>>();
    if ((T & 1u) == 0)
        fused_kernel<true><<<P / 64, 256>>>(x, mask, (const float4*)Wg,
                                            out, P, T);
    else
        fused_kernel<false><<<P / 64, 256>>>(x, mask, (const float4*)Wg,
                                             out, P, T);
}

// round 11
// speedup vs baseline: 1.2940x; 1.2940x over previous
#include <cuda_runtime.h>

#define PATCH 32
#define MAXP  65536
#define NREAL 3

// Scratch (no allocations allowed)
__device__ float2 g_w2[MAXP];        // top-2 softmax scores per patch
__device__ int    g_meta[MAXP];      // i0 | i1<<8 | lvl<<16
__device__ int    g_start[MAXP];     // exclusive scan of counts
__device__ int    g_bsum[1024];      // per-64-patch block count sums

// ---------------------------------------------------------------------------
// Kernel 1: gate. 4 threads per patch; thread qt owns elements [8qt, 8qt+8),
// FMA-chain partial dots for all 4 experts, quad shfl_xor completes logits.
// Top-2 selected on RAW LOGITS (softmax is monotonic -> identical routing);
// score values via __expf/__fdividef (only feeds output weights, ~1e-6 rel).
// Fused per-block count sum. 64 patches/block, 1024 blocks.
// ---------------------------------------------------------------------------
__global__ void gate_kernel(const float4* __restrict__ x4,
                            const float4* __restrict__ Wg4, int P) {
    __shared__ float4 wg4[32];           // 4 experts x 8 quads
    __shared__ int wsum[8];
    int t = threadIdx.x;
    int lane = t & 31;
    int qt = t & 3;
    if (t < 32) wg4[t] = Wg4[t];
    __syncthreads();

    int p = blockIdx.x * 64 + (t >> 2);

    float4 xa = x4[(unsigned)p * 8u + qt * 2];
    float4 xb = x4[(unsigned)p * 8u + qt * 2 + 1];

    float d[4];
#pragma unroll
    for (int e = 0; e < 4; e++) {
        float4 wa = wg4[e * 8 + qt * 2];
        float4 wb = wg4[e * 8 + qt * 2 + 1];
        float s = xa.x * wa.x;
        s = fmaf(xa.y, wa.y, s);
        s = fmaf(xa.z, wa.z, s);
        s = fmaf(xa.w, wa.w, s);
        s = fmaf(xb.x, wb.x, s);
        s = fmaf(xb.y, wb.y, s);
        s = fmaf(xb.z, wb.z, s);
        s = fmaf(xb.w, wb.w, s);
        d[e] = s;
    }
#pragma unroll
    for (int e = 0; e < 4; e++) {
        d[e] += __shfl_xor_sync(0xffffffffu, d[e], 1);
        d[e] += __shfl_xor_sync(0xffffffffu, d[e], 2);
    }

    // top-2 on raw logits (exact ordering)
    int i0 = 0;
#pragma unroll
    for (int i = 1; i < 4; i++) if (d[i] > d[i0]) i0 = i;
    int i1 = -1;
#pragma unroll
    for (int i = 0; i < 4; i++)
        if (i != i0 && (i1 < 0 || d[i] > d[i1])) i1 = i;
    int lv = -1;
    if (i0 < NREAL) lv = max(lv, i0);
    if (i1 < NREAL) lv = max(lv, i1);
    int lvl = max(lv, 0);

    // scores: fast exp (weights output only; routing already fixed above)
    float m = fmaxf(fmaxf(d[0], d[1]), fmaxf(d[2], d[3]));
    float e0 = __expf(d[0] - m), e1 = __expf(d[1] - m);
    float e2 = __expf(d[2] - m), e3 = __expf(d[3] - m);
    float inv = __fdividef(1.f, e0 + e1 + e2 + e3);
    float ea[4] = {e0, e1, e2, e3};

    if (qt == 0 && p < P) {
        g_w2[p] = make_float2(ea[i0] * inv, ea[i1] * inv);
        g_meta[p] = i0 | (i1 << 8) | (lvl << 16);
    }
    int cnt = (qt == 0 && p < P) ? (1 << lvl) : 0;
    int ws = __reduce_add_sync(0xffffffffu, cnt);
    if (lane == 0) wsum[t >> 5] = ws;
    __syncthreads();
    if (t == 0) {
        int sum = 0;
#pragma unroll
        for (int i = 0; i < 8; i++) sum += wsum[i];
        g_bsum[blockIdx.x] = sum;
    }
}

// ---------------------------------------------------------------------------
// Kernel 2: per-patch starts. Block offset = redundant reduce of preceding
// 64-patch sums (4*bid entries from L2), then intra-block shfl scan.
// ---------------------------------------------------------------------------
__global__ void starts_kernel(int P) {
    __shared__ int ws[8];
    __shared__ int bofs;
    int t = threadIdx.x, lane = t & 31, wp = t >> 5;
    int p = blockIdx.x * 256 + t;

    int lim = blockIdx.x * 4;
    int bo = (t < lim) ? g_bsum[t] : 0;
    for (int i = t + 256; i < lim; i += 256) bo += g_bsum[i];
    bo = __reduce_add_sync(0xffffffffu, bo);
    if (lane == 0) ws[wp] = bo;
    __syncthreads();
    if (t == 0) {
        int s = 0;
#pragma unroll
        for (int i = 0; i < 8; i++) s += ws[i];
        bofs = s;
    }
    __syncthreads();

    int cnt = (p < P) ? (1 << ((g_meta[p] >> 16) & 3)) : 0;
    int inc = cnt;
#pragma unroll
    for (int o = 1; o < 32; o <<= 1) {
        int u = __shfl_up_sync(0xffffffffu, inc, o);
        if (lane >= o) inc += u;
    }
    __syncthreads();
    if (lane == 31) ws[wp] = inc;
    __syncthreads();
    if (wp == 0) {
        int s = (lane < 8) ? ws[lane] : 0;
#pragma unroll
        for (int o = 1; o < 8; o <<= 1) {
            int u = __shfl_up_sync(0xffffffffu, s, o);
            if (lane >= o) s += u;
        }
        if (lane < 8) ws[lane] = s;
    }
    __syncthreads();
    int off = wp ? ws[wp - 1] : 0;
    if (p < P) g_start[p] = bofs + off + inc - cnt;
}

// ---------------------------------------------------------------------------
// Kernel 3: writer, ONE WARP per patch (round-9, proven). new_x/new_mask via
// STG.128; x_final via lvl-specialized coalesced scalar stores (T odd in
// practice); EVEN float2 path kept for the T-even case.
// Output layout (floats):
//   [0,32T) new_x   [32T,64T) new_mask  [64T,65T) new_size
//   [65T,67T) weights  [67T,69T) expert_idx  [69T,165T) x_final [T,3,32]
// ---------------------------------------------------------------------------
template <bool EVEN>
__global__ void write_kernel(const float* __restrict__ x,
                             const float* __restrict__ mask,
                             float* __restrict__ out, int P, unsigned T) {
    unsigned w = (blockIdx.x * blockDim.x + threadIdx.x) >> 5;
    unsigned lane = threadIdx.x & 31;
    if (w >= (unsigned)P) return;

    int meta = g_meta[w];
    unsigned start = (unsigned)g_start[w];
    int i0 = meta & 255, i1 = (meta >> 8) & 255, lvl = (meta >> 16) & 3;
    int cnt = 1 << lvl, sz = 32 >> lvl;

    // ---- new_x / new_mask: always 16B-aligned vector stores ----
    {
        const float4* xp = (const float4*)x + (unsigned)w * 8u;
        const float4* mp = (const float4*)mask + (unsigned)w * 8u;
        int c = lane >> 3, q = lane & 7;
        bool qv = (q * 4) < sz;
        int gi = qv ? ((c * sz) >> 2) + q : 0;
        float4 gx = xp[gi];
        float4 gm = mp[gi];
        if (!qv) { gx = make_float4(0.f,0.f,0.f,0.f);
                   gm = make_float4(0.f,0.f,0.f,0.f); }
        if (c < cnt) {
            float4* out4 = (float4*)out;
            unsigned idx4 = (start + c) * 8u + q;
            out4[idx4] = gx;
            out4[T * 8u + idx4] = gm;
        }
    }

    // ---- small fields ----
    float* ps = out + T * 64u + start;
    float* pw = out + T * 65u + start * 2u + lane;
    float* pe = out + T * 67u + start * 2u + lane;
    if (lane < (unsigned)cnt) ps[lane] = (float)sz;
    if (lane < (unsigned)(cnt * 2)) {
        float2 wv = g_w2[w];
        pw[0] = (lane & 1) ? wv.y : wv.x;
        pe[0] = (float)((lane & 1) ? i1 : i0);
    }

    // ---- x_final ----
    if (EVEN) {
        unsigned q16 = lane & 15u, h = lane >> 4;
        float2 xw = ((const float2*)x)[w * 16u + q16];
        float2 mw = ((const float2*)mask)[w * 16u + q16];
        float2 pm2 = make_float2(xw.x * mw.x, xw.y * mw.y);
        const float2 z2 = make_float2(0.f, 0.f);
        int rows = 3 * cnt;
        int j0 = (int)(q16 * 2u);
        unsigned b2 = (T >> 1) * 69u + start * 48u + q16;   // float2 units
#pragma unroll
        for (int rb = 0; rb < 12; rb += 2) {
            if (rb >= rows) break;
            int row = rb + (int)h;
            int c = (row * 11) >> 5;       // row/3 for row<12
            int l = row - 3 * c;
            bool on = false;
            if (l == lvl) {
                int lo = c * sz; on = (j0 >= lo) & (j0 < lo + sz);
            } else if (lvl >= 1 && l == lvl - 1) {
                int lo = (c >> 1) * (sz * 2);
                on = (j0 >= lo) & (j0 < lo + sz * 2);
            }
            float2 v = on ? pm2 : z2;
            if (row < rows) ((float2*)out)[b2 + (unsigned)row * 16u] = v;
        }
    } else {
        float xv = x[w * 32u + lane];
        float mv = mask[w * 32u + lane];
        float pm = xv * mv;
        float* pf = out + T * 69u + start * 96u + lane;
        switch (lvl) {
        case 0:
            pf[0] = pm;  pf[32] = 0.f;  pf[64] = 0.f;
            break;
        case 1: {
            bool lo = lane < 16, hi = !lo;
            pf[0]  = pm;  pf[32]  = lo ? pm : 0.f;  pf[64]  = 0.f;
            pf[96] = pm;  pf[128] = hi ? pm : 0.f;  pf[160] = 0.f;
            break;
        }
        default: {
            bool h0 = lane < 16, h1 = !h0;
            bool o0 = lane < 8, o1 = (lane >= 8) & h0;
            bool o2 = (lane >= 16) & (lane < 24), o3 = lane >= 24;
            pf[0]   = 0.f;  pf[32]  = h0 ? pm : 0.f;  pf[64]  = o0 ? pm : 0.f;
            pf[96]  = 0.f;  pf[128] = h0 ? pm : 0.f;  pf[160] = o1 ? pm : 0.f;
            pf[192] = 0.f;  pf[224] = h1 ? pm : 0.f;  pf[256] = o2 ? pm : 0.f;
            pf[288] = 0.f;  pf[320] = h1 ? pm : 0.f;  pf[352] = o3 ? pm : 0.f;
            break;
        }
        }
    }
}

// ---------------------------------------------------------------------------
extern "C" void kernel_launch(void* const* d_in, const int* in_sizes, int n_in,
                              void* d_out, int out_size) {
    const float* x    = (const float*)d_in[0];
    const float* mask = (const float*)d_in[1];
    const float* Wg   = (const float*)d_in[2];
    float* out = (float*)d_out;

    int n = in_sizes[0];
    int P = n / PATCH;                 // 65536
    unsigned T = (unsigned)(out_size / 165);

    gate_kernel<<<(P + 63) / 64, 256>>>((const float4*)x, (const float4*)Wg, P);
    starts_kernel<<<(P + 255) / 256, 256>>>(P);
    int wb = (P * 32 + 255) / 256;
    if ((T & 1u) == 0)
        write_kernel<true><<<wb, 256>>>(x, mask, out, P, T);
    else
        write_kernel<false><<<wb, 256>>>(x, mask, out, P, T);
}